// round 17
// baseline (speedup 1.0000x reference)
#include <cuda_runtime.h>

#define BB 128
#define SS 512
#define KK 4
#define DD 300
#define CC 20
#define NN 10000
#define PROW 32                    // padded P row: 128B, line-aligned

// K1: 16 nodes/block; thread = (dc 0..4, pair 0..7, cg 0..3) -> 160 threads
#define DSPLIT 5
#define DCH (DD / DSPLIT)          // 60
#define P1_TPB 160
#define P1_NODES 16
#define P1_GRID ((NN + P1_NODES - 1) / P1_NODES)   // 625
#define P1_THREADS (P1_GRID * P1_TPB)              // 100000

// K2: grid (2, BB), 256 threads; warp = 32 s-positions, lane = one s
#define GCH 2
#define SCH (SS / GCH)             // 256
#define G_TPB 256
#define NWARP (G_TPB / 32)         // 8

#define EWN (BB * SS * KK)         // 262144

__device__ __align__(128) float g_P[NN * PROW];   // padded P (1.28 MB, L2-resident)
__device__ float g_EW[EWN];              // prefetched edge weights (1 MB)
__device__ float g_part[BB * GCH * CC];  // per-(b,chunk) logit partials
__device__ unsigned int g_done[BB];      // zero-init; self-resets each call

#define FMA2(acc, a, b) \
    asm("fma.rn.f32x2 %0, %1, %2, %0;" : "+l"(acc) : "l"(a), "l"(b))

__device__ __forceinline__ float f32x2_sum(unsigned long long v) {
    float lo = __uint_as_float((unsigned)(v & 0xffffffffull));
    float hi = __uint_as_float((unsigned)(v >> 32));
    return lo + hi;
}

// ---------------------------------------------------------------------------
// K1 (R16 verbatim): f32x2 P-GEMM + overlapped random edge_w prefetch.
// ---------------------------------------------------------------------------
__global__ void __launch_bounds__(P1_TPB, 7) p_kernel(
    const float* __restrict__ node_emb, const float* __restrict__ fc_w,
    const int* __restrict__ EW, const float* __restrict__ edge_w)
{
    __shared__ __align__(16) float sF[DSPLIT * CC * DCH];   // 24 KB [dc][c][d]
    __shared__ float sAcc[DSPLIT][P1_NODES * CC];           // 6.4 KB

    const int t = threadIdx.x;

    for (int i = t; i < DSPLIT * CC * DCH; i += P1_TPB) {
        const int dc = i / (CC * DCH);
        const int r  = i % (CC * DCH);
        sF[i] = fc_w[(r / DCH) * DD + dc * DCH + (r % DCH)];
    }

    for (int i = blockIdx.x * P1_TPB + t; i < EWN; i += P1_THREADS)
        g_EW[i] = __ldg(&edge_w[__ldg(&EW[i])]);

    __syncthreads();

    const int dc = t >> 5;                 // 0..4
    const int w  = t & 31;
    const int pr = w >> 2;                 // 0..7 node-pair
    const int cg = w & 3;                  // 0..3 class-group (5 classes)
    const int n0 = blockIdx.x * P1_NODES + pr * 2;
    const int d0 = dc * DCH;

    if (n0 < NN) {
        const ulonglong2* __restrict__ e0 =
            (const ulonglong2*)(node_emb + (size_t)n0 * DD + d0);
        const ulonglong2* __restrict__ e1 =
            (const ulonglong2*)(node_emb + (size_t)(n0 + 1) * DD + d0);
        const ulonglong2* __restrict__ f4 =
            (const ulonglong2*)(sF + dc * CC * DCH + cg * 5 * DCH);

        unsigned long long a0[5] = {0, 0, 0, 0, 0};
        unsigned long long a1[5] = {0, 0, 0, 0, 0};
        #pragma unroll
        for (int dq = 0; dq < DCH / 4; dq++) {       // 15 iters
            const ulonglong2 v0 = e0[dq];
            const ulonglong2 v1 = e1[dq];
            #pragma unroll
            for (int c5 = 0; c5 < 5; c5++) {
                const ulonglong2 fv = f4[c5 * (DCH / 4) + dq];
                FMA2(a0[c5], v0.x, fv.x);
                FMA2(a0[c5], v0.y, fv.y);
                FMA2(a1[c5], v1.x, fv.x);
                FMA2(a1[c5], v1.y, fv.y);
            }
        }
        #pragma unroll
        for (int c5 = 0; c5 < 5; c5++) {
            sAcc[dc][(pr * 2    ) * CC + cg * 5 + c5] = f32x2_sum(a0[c5]);
            sAcc[dc][(pr * 2 + 1) * CC + cg * 5 + c5] = f32x2_sum(a1[c5]);
        }
    }
    __syncthreads();

    const int nb = blockIdx.x * P1_NODES;
    for (int i = t; i < P1_NODES * CC; i += P1_TPB) {
        const int nl = i / CC, c = i % CC;
        if (nb + nl < NN) {
            float s = sAcc[0][i];
            #pragma unroll
            for (int d = 1; d < DSPLIT; d++) s += sAcc[d][i];
            g_P[(size_t)(nb + nl) * PROW + c] = s;
        }
    }
}

// ---------------------------------------------------------------------------
// K2: warp-autonomous gather. Lane = one s-position: 25 independent float4
// P-row loads (MLP 800/warp), 20 class accs in registers, butterfly reduce,
// ONE block barrier, last-arriving chunk block per b finalizes.
// ---------------------------------------------------------------------------
__global__ void __launch_bounds__(G_TPB, 2) gather_kernel(
    const int* __restrict__ X, const int* __restrict__ NX,
    const float* __restrict__ node_w,
    const float* __restrict__ fc_b, float* __restrict__ out)
{
    __shared__ float sred[NWARP][CC];

    const int b    = blockIdx.y;
    const int ch   = blockIdx.x;
    const int t    = threadIdx.x;
    const int warp = t >> 5;
    const int lane = t & 31;
    const int s    = b * SS + ch * SCH + warp * 32 + lane;   // global s-index

    // Per-lane coalesced index/scalar loads; node_w is the only dependent chain
    const int    x   = X[s];
    const int4   nx  = ((const int4*)NX)[s];
    const float4 ew  = ((const float4*)g_EW)[s];     // pre-resolved by K1
    const float  nw  = __ldg(&node_w[x]);

    const float4* __restrict__ P4 = (const float4*)g_P;     // row stride 8
    const float inw = 1.f - nw;

    float acc[CC];
    // q-loop fully unrolled: 25 independent LDG.128 hoisted by scheduler
    #pragma unroll
    for (int q = 0; q < 5; q++) {
        const float4 p0 = __ldg(&P4[(size_t)nx.x * 8 + q]);
        const float4 p1 = __ldg(&P4[(size_t)nx.y * 8 + q]);
        const float4 p2 = __ldg(&P4[(size_t)nx.z * 8 + q]);
        const float4 p3 = __ldg(&P4[(size_t)nx.w * 8 + q]);
        const float4 pr = __ldg(&P4[(size_t)x    * 8 + q]);
        #pragma unroll
        for (int j = 0; j < 4; j++) {
            const float m = ew.x * (&p0.x)[j] + ew.y * (&p1.x)[j]
                          + ew.z * (&p2.x)[j] + ew.w * (&p3.x)[j];
            acc[q * 4 + j] = inw * m + nw * (&pr.x)[j];
        }
    }

    // Butterfly over 32 lanes (fixed order -> deterministic)
    #pragma unroll
    for (int o = 16; o; o >>= 1)
        #pragma unroll
        for (int c = 0; c < CC; c++)
            acc[c] += __shfl_xor_sync(0xffffffffu, acc[c], o);

    if (lane == 0) {
        #pragma unroll
        for (int q = 0; q < 5; q++)
            *(float4*)&sred[warp][q * 4] =
                make_float4(acc[q * 4], acc[q * 4 + 1], acc[q * 4 + 2], acc[q * 4 + 3]);
    }
    __syncthreads();                       // the ONE block barrier

    // Warp 0: fixed-order sum over 8 warps, publish, maybe finalize
    if (warp == 0) {
        float v = 0.f;
        if (lane < CC) {
            #pragma unroll
            for (int w8 = 0; w8 < NWARP; w8++) v += sred[w8][lane];
            g_part[(b * GCH + ch) * CC + lane] = v;
        }

        unsigned last = 0;
        if (lane == 0) {
            __threadfence();                               // release my partial
            last = (atomicAdd(&g_done[b], 1u) == GCH - 1) ? 1u : 0u;
        }
        last = __shfl_sync(0xffffffffu, last, 0);
        if (last) {
            if (lane == 0) {
                g_done[b] = 0;                             // reset for replay
                __threadfence();                           // acquire partials
            }
            __syncwarp();
            float l = -1e30f;
            if (lane < CC) {
                float sacc = fc_b[lane];
                #pragma unroll
                for (int q = 0; q < GCH; q++)
                    sacc += g_part[(b * GCH + q) * CC + lane];
                l = fmaxf(sacc, 0.f);
            }
            float mx = l;
            #pragma unroll
            for (int o = 16; o; o >>= 1) mx = fmaxf(mx, __shfl_xor_sync(0xffffffffu, mx, o));
            const float e = (lane < CC) ? __expf(l - mx) : 0.f;
            float sum = e;
            #pragma unroll
            for (int o = 16; o; o >>= 1) sum += __shfl_xor_sync(0xffffffffu, sum, o);
            if (lane < CC) out[b * CC + lane] = e / sum;
        }
    }
}

// ---------------------------------------------------------------------------
extern "C" void kernel_launch(void* const* d_in, const int* in_sizes, int n_in,
                              void* d_out, int out_size)
{
    const int*   X        = (const int*)  d_in[0];
    const int*   NX       = (const int*)  d_in[1];
    const int*   EW       = (const int*)  d_in[2];
    const float* node_emb = (const float*)d_in[3];
    const float* edge_w   = (const float*)d_in[4];
    const float* node_w   = (const float*)d_in[5];
    const float* fc_w     = (const float*)d_in[6];
    const float* fc_b     = (const float*)d_in[7];
    float* out = (float*)d_out;

    p_kernel<<<P1_GRID, P1_TPB>>>(node_emb, fc_w, EW, edge_w);
    dim3 grid2(GCH, BB);
    gather_kernel<<<grid2, G_TPB>>>(X, NX, node_w, fc_b, out);
}